// round 1
// baseline (speedup 1.0000x reference)
#include <cuda_runtime.h>
#include <cuda_bf16.h>
#include <math.h>

// Problem constants (CrossAttention_24008867184861)
#define BQ   2
#define SQ   2048
#define SK   2048
#define HQ   16
#define HKV  4
#define GRP  (HQ / HKV)   // 4
#define DH   64
#define NEGV (-10000.0f)
#define SCALE 0.125f       // 1/sqrt(64)

#define TS 64              // tile size (rows/cols)
#define TP 68              // padded row stride in floats (17 float4s -> conflict-free)
#define NTHREADS 256

__device__ float g_maskBias[BQ * SK];   // 0.0f valid, -10000.0f padded

// ---------------------------------------------------------------------------
// Kernel 0: detect mask dtype (bool/uint8 vs int32) and expand to fp32 bias.
// int32 0/1 values have every byte at offset %4 != 0 equal to zero; a random
// bool array does not. Deterministic given the input.
// ---------------------------------------------------------------------------
__global__ void mask_expand_kernel(const void* __restrict__ mask) {
    int tid = threadIdx.x;
    const unsigned char* mb = (const unsigned char*)mask;
    bool odd_nonzero = false;
    for (int i = tid; i < BQ * SK; i += NTHREADS)
        if ((i & 3) && mb[i]) odd_nonzero = true;
    bool is_byte = __syncthreads_or(odd_nonzero);
    const int* mi = (const int*)mask;
    for (int i = tid; i < BQ * SK; i += NTHREADS) {
        int v = is_byte ? (int)mb[i] : mi[i];
        g_maskBias[i] = v ? 0.0f : NEGV;
    }
}

// ---------------------------------------------------------------------------
// Kernel 1: flash attention, fp32, 64x64 tiles, 4x4 per-thread register tile.
// Processes only tiles intersecting the causal region. Exact (bit-matching
// the fp32 reference up to reduction-order noise) for every row that has at
// least one unpadded visible key, because exp(-10000 - O(1)) == 0 in fp32.
// ---------------------------------------------------------------------------
__global__ void __launch_bounds__(NTHREADS)
fa_kernel(const float* __restrict__ q, const float* __restrict__ kv,
          float* __restrict__ out) {
    extern __shared__ float sm[];
    float* Qs = sm;                 // [TS][TP]
    float* Ks = Qs + TS * TP;       // [TS][TP]
    float* Vs = Ks + TS * TP;       // [TS][TP]
    float* Ps = Vs + TS * TP;       // [TS][TP]
    __shared__ float biasS[TS];

    const int qt  = (SQ / TS - 1) - blockIdx.x;   // heavy tiles first
    const int bh  = blockIdx.y;
    const int b   = bh / HQ;
    const int h   = bh % HQ;
    const int hkv = h / GRP;
    const int m0  = qt * TS;

    const int tid = threadIdx.x;
    const int tx  = tid & 15;
    const int ty  = tid >> 4;

    // ---- load Q tile (rows m0..m0+63) ----
    const float* qg = q + ((size_t)(b * SQ + m0) * HQ + h) * DH;
    for (int i = tid; i < TS * (DH / 4); i += NTHREADS) {
        int r = i >> 4, f = i & 15;
        float4 v = *(const float4*)(qg + (size_t)r * HQ * DH + f * 4);
        *(float4*)&Qs[r * TP + f * 4] = v;
    }

    float m_i[4], l_i[4], O[4][4];
#pragma unroll
    for (int i = 0; i < 4; i++) {
        m_i[i] = -1e30f; l_i[i] = 0.0f;
#pragma unroll
        for (int j = 0; j < 4; j++) O[i][j] = 0.0f;
    }

    const int ntiles = qt + 1;   // Sk == Sq -> diag at tile qt

    for (int jt = 0; jt < ntiles; ++jt) {
        const int n0 = jt * TS;
        __syncthreads();   // previous iteration's Ks/Vs/Ps fully consumed

        // ---- load K and V tiles ----
        for (int i = tid; i < TS * (DH / 4); i += NTHREADS) {
            int r = i >> 4, f = i & 15;
            size_t off = (((size_t)(b * SK + n0 + r) * 2) * HKV + hkv) * DH + f * 4;
            float4 kvk = *(const float4*)(kv + off);
            *(float4*)&Ks[r * TP + f * 4] = kvk;
            float4 kvv = *(const float4*)(kv + off + (size_t)HKV * DH);
            *(float4*)&Vs[r * TP + f * 4] = kvv;
        }
        if (tid < TS) biasS[tid] = g_maskBias[b * SK + n0 + tid];
        __syncthreads();

        // ---- S = Q K^T (4x4 per thread) ----
        float S[4][4];
#pragma unroll
        for (int i = 0; i < 4; i++)
#pragma unroll
            for (int j = 0; j < 4; j++) S[i][j] = 0.0f;

#pragma unroll 4
        for (int dc = 0; dc < DH / 4; dc++) {
            float4 qf[4], kf[4];
#pragma unroll
            for (int i = 0; i < 4; i++)
                qf[i] = *(const float4*)&Qs[(ty * 4 + i) * TP + dc * 4];
#pragma unroll
            for (int j = 0; j < 4; j++)
                kf[j] = *(const float4*)&Ks[(tx * 4 + j) * TP + dc * 4];
#pragma unroll
            for (int i = 0; i < 4; i++)
#pragma unroll
                for (int j = 0; j < 4; j++) {
                    S[i][j] += qf[i].x * kf[j].x;
                    S[i][j] += qf[i].y * kf[j].y;
                    S[i][j] += qf[i].z * kf[j].z;
                    S[i][j] += qf[i].w * kf[j].w;
                }
        }

        // ---- scale + padding bias + causal (replace) ----
        const bool diag = (jt == qt);
        float bj[4];
#pragma unroll
        for (int j = 0; j < 4; j++) bj[j] = biasS[tx * 4 + j];
#pragma unroll
        for (int i = 0; i < 4; i++) {
            int r = m0 + ty * 4 + i;
#pragma unroll
            for (int j = 0; j < 4; j++) {
                int c = n0 + tx * 4 + j;
                float s = S[i][j] * SCALE + bj[j];
                if (diag && c > r) s = NEGV;
                S[i][j] = s;
            }
        }

        // ---- online softmax (row reductions across 16 lanes via shfl) ----
        float m_new[4], alpha[4], rs[4];
#pragma unroll
        for (int i = 0; i < 4; i++) {
            float rm = fmaxf(fmaxf(S[i][0], S[i][1]), fmaxf(S[i][2], S[i][3]));
#pragma unroll
            for (int w = 1; w < 16; w <<= 1)
                rm = fmaxf(rm, __shfl_xor_sync(0xffffffffu, rm, w));
            m_new[i] = fmaxf(m_i[i], rm);
            alpha[i] = __expf(m_i[i] - m_new[i]);
            float s0 = __expf(S[i][0] - m_new[i]);
            float s1 = __expf(S[i][1] - m_new[i]);
            float s2 = __expf(S[i][2] - m_new[i]);
            float s3 = __expf(S[i][3] - m_new[i]);
            S[i][0] = s0; S[i][1] = s1; S[i][2] = s2; S[i][3] = s3;
            float sum = s0 + s1 + s2 + s3;
#pragma unroll
            for (int w = 1; w < 16; w <<= 1)
                sum += __shfl_xor_sync(0xffffffffu, sum, w);
            rs[i] = sum;
        }
#pragma unroll
        for (int i = 0; i < 4; i++) {
            l_i[i] = l_i[i] * alpha[i] + rs[i];
            m_i[i] = m_new[i];
#pragma unroll
            for (int j = 0; j < 4; j++) O[i][j] *= alpha[i];
        }

        // ---- write P to smem ----
#pragma unroll
        for (int i = 0; i < 4; i++) {
            float4 pv = make_float4(S[i][0], S[i][1], S[i][2], S[i][3]);
            *(float4*)&Ps[(ty * 4 + i) * TP + tx * 4] = pv;
        }
        __syncthreads();

        // ---- O += P V ----
#pragma unroll 4
        for (int kc = 0; kc < TS / 4; kc++) {
            float4 pf[4], vf[4];
#pragma unroll
            for (int i = 0; i < 4; i++)
                pf[i] = *(const float4*)&Ps[(ty * 4 + i) * TP + kc * 4];
#pragma unroll
            for (int qq = 0; qq < 4; qq++)
                vf[qq] = *(const float4*)&Vs[(kc * 4 + qq) * TP + tx * 4];
#pragma unroll
            for (int i = 0; i < 4; i++) {
                O[i][0] += pf[i].x * vf[0].x + pf[i].y * vf[1].x + pf[i].z * vf[2].x + pf[i].w * vf[3].x;
                O[i][1] += pf[i].x * vf[0].y + pf[i].y * vf[1].y + pf[i].z * vf[2].y + pf[i].w * vf[3].y;
                O[i][2] += pf[i].x * vf[0].z + pf[i].y * vf[1].z + pf[i].z * vf[2].z + pf[i].w * vf[3].z;
                O[i][3] += pf[i].x * vf[0].w + pf[i].y * vf[1].w + pf[i].z * vf[2].w + pf[i].w * vf[3].w;
            }
        }
    }

    // ---- epilogue ----
#pragma unroll
    for (int i = 0; i < 4; i++) {
        float inv = 1.0f / l_i[i];
        float4 ov = make_float4(O[i][0] * inv, O[i][1] * inv, O[i][2] * inv, O[i][3] * inv);
        size_t off = ((size_t)(b * SQ + m0 + ty * 4 + i) * HQ + h) * DH + tx * 4;
        *(float4*)(out + off) = ov;
    }
}

// ---------------------------------------------------------------------------
// Kernel 2: fix-up for degenerate rows (all causally-visible keys padded).
// For those rows the -10000 "causal" tail carries O(1) softmax weight, so the
// flash kernel (which skips past-diagonal tiles) is wrong there. Recompute
// the full row exactly and overwrite. ~1-2 rows per batch -> negligible cost.
// ---------------------------------------------------------------------------
__global__ void __launch_bounds__(NTHREADS)
fix_degenerate_kernel(const float* __restrict__ q, const float* __restrict__ kv,
                      float* __restrict__ out) {
    const int b = blockIdx.x / SQ;
    const int r = blockIdx.x % SQ;
    const int tid = threadIdx.x;
    const int vis = r;   // Sk == Sq -> visible cols are [0, r]

    bool any_valid = false;
    for (int s = tid; s <= vis; s += NTHREADS)
        if (g_maskBias[b * SK + s] == 0.0f) any_valid = true;
    if (__syncthreads_or(any_valid)) return;   // non-degenerate: flash result exact

    __shared__ float sc[SK];
    __shared__ float red[NTHREADS];

    for (int h = 0; h < HQ; h++) {
        const int hkv = h / GRP;
        const float* qr = q + ((size_t)(b * SQ + r) * HQ + h) * DH;

        for (int c = tid; c < SK; c += NTHREADS) {
            const float* kr = kv + (((size_t)(b * SK + c) * 2) * HKV + hkv) * DH;
            float acc = 0.0f;
#pragma unroll 8
            for (int d = 0; d < DH; d++) acc += qr[d] * kr[d];
            float s = acc * SCALE + g_maskBias[b * SK + c];
            if (c > vis) s = NEGV;
            sc[c] = s;
        }
        __syncthreads();

        float lm = -1e30f;
        for (int c = tid; c < SK; c += NTHREADS) lm = fmaxf(lm, sc[c]);
        red[tid] = lm;
        __syncthreads();
        for (int st = NTHREADS / 2; st > 0; st >>= 1) {
            if (tid < st) red[tid] = fmaxf(red[tid], red[tid + st]);
            __syncthreads();
        }
        float m = red[0];
        __syncthreads();

        float ls = 0.0f;
        for (int c = tid; c < SK; c += NTHREADS) {
            float p = __expf(sc[c] - m);
            sc[c] = p;
            ls += p;
        }
        red[tid] = ls;
        __syncthreads();
        for (int st = NTHREADS / 2; st > 0; st >>= 1) {
            if (tid < st) red[tid] += red[tid + st];
            __syncthreads();
        }
        float l = red[0];
        __syncthreads();

        const int dq = tid & 63;
        const int ch = tid >> 6;                  // 4 chunks of 512 cols
        float acc = 0.0f;
        for (int c = ch * (SK / 4); c < (ch + 1) * (SK / 4); c++)
            acc += sc[c] * kv[(((size_t)(b * SK + c) * 2 + 1) * HKV + hkv) * DH + dq];
        red[tid] = acc;
        __syncthreads();
        if (tid < DH) {
            float o = red[tid] + red[tid + 64] + red[tid + 128] + red[tid + 192];
            out[((size_t)(b * SQ + r) * HQ + h) * DH + tid] = o / l;
        }
        __syncthreads();
    }
}

// ---------------------------------------------------------------------------
extern "C" void kernel_launch(void* const* d_in, const int* in_sizes, int n_in,
                              void* d_out, int out_size) {
    const float* q    = (const float*)d_in[0];
    const float* kv   = (const float*)d_in[1];
    const void*  mask = d_in[2];
    float* out = (float*)d_out;

    const int smem_bytes = 4 * TS * TP * sizeof(float);   // 69632
    static bool attr_set = false;
    if (!attr_set) {
        cudaFuncSetAttribute(fa_kernel,
                             cudaFuncAttributeMaxDynamicSharedMemorySize,
                             smem_bytes);
        attr_set = true;
    }

    mask_expand_kernel<<<1, NTHREADS>>>(mask);
    dim3 grid(SQ / TS, BQ * HQ);
    fa_kernel<<<grid, NTHREADS, smem_bytes>>>(q, kv, out);
    fix_degenerate_kernel<<<BQ * SQ, NTHREADS>>>(q, kv, out);
}

// round 2
// speedup vs baseline: 1.1948x; 1.1948x over previous
#include <cuda_runtime.h>
#include <cuda_bf16.h>
#include <math.h>

// Problem constants (CrossAttention_24008867184861)
#define BQ   2
#define SQ   2048
#define SK   2048
#define HQ   16
#define HKV  4
#define GRP  (HQ / HKV)   // 4
#define DH   64
#define NEGV (-10000.0f)
#define SCALE 0.125f       // 1/sqrt(64)

#define TS 64              // tile size (rows/cols)
#define TP 68              // padded row stride in floats
#define FA_THREADS 128
#define NTHREADS 256

__device__ float g_maskBias[BQ * SK];   // 0.0f valid, -10000.0f padded

// ---------------------------------------------------------------------------
// Kernel 0: detect mask dtype (bool/uint8 vs int32) and expand to fp32 bias.
// ---------------------------------------------------------------------------
__global__ void mask_expand_kernel(const void* __restrict__ mask) {
    int tid = threadIdx.x;
    const unsigned char* mb = (const unsigned char*)mask;
    bool odd_nonzero = false;
    for (int i = tid; i < BQ * SK; i += 256)
        if ((i & 3) && mb[i]) odd_nonzero = true;
    bool is_byte = __syncthreads_or(odd_nonzero);
    const int* mi = (const int*)mask;
    for (int i = blockIdx.x * 256 + tid; i < BQ * SK; i += gridDim.x * 256) {
        int v = is_byte ? (int)mb[i] : mi[i];
        g_maskBias[i] = v ? 0.0f : NEGV;
    }
}

// ---------------------------------------------------------------------------
// Kernel 1: fix-up for degenerate rows (all causally-visible keys padded).
// Runs BEFORE the flash kernel; writes only degenerate rows, which the flash
// kernel skips. Disjoint writes -> order-independent correctness.
// ---------------------------------------------------------------------------
__global__ void __launch_bounds__(NTHREADS)
fix_degenerate_kernel(const float* __restrict__ q, const float* __restrict__ kv,
                      float* __restrict__ out) {
    const int b = blockIdx.x / SQ;
    const int r = blockIdx.x % SQ;
    const int tid = threadIdx.x;
    const int vis = r;   // Sk == Sq -> visible cols are [0, r]

    bool any_valid = false;
    for (int s = tid; s <= vis; s += NTHREADS)
        if (g_maskBias[b * SK + s] == 0.0f) any_valid = true;
    if (__syncthreads_or(any_valid)) return;   // non-degenerate

    __shared__ float sc[SK];
    __shared__ float red[NTHREADS];

    for (int h = 0; h < HQ; h++) {
        const int hkv = h / GRP;
        const float* qr = q + ((size_t)(b * SQ + r) * HQ + h) * DH;

        for (int c = tid; c < SK; c += NTHREADS) {
            const float* kr = kv + (((size_t)(b * SK + c) * 2) * HKV + hkv) * DH;
            float acc = 0.0f;
#pragma unroll 8
            for (int d = 0; d < DH; d++) acc += qr[d] * kr[d];
            float s = acc * SCALE + g_maskBias[b * SK + c];
            if (c > vis) s = NEGV;
            sc[c] = s;
        }
        __syncthreads();

        float lm = -1e30f;
        for (int c = tid; c < SK; c += NTHREADS) lm = fmaxf(lm, sc[c]);
        red[tid] = lm;
        __syncthreads();
        for (int st = NTHREADS / 2; st > 0; st >>= 1) {
            if (tid < st) red[tid] = fmaxf(red[tid], red[tid + st]);
            __syncthreads();
        }
        float m = red[0];
        __syncthreads();

        float ls = 0.0f;
        for (int c = tid; c < SK; c += NTHREADS) {
            float p = __expf(sc[c] - m);
            sc[c] = p;
            ls += p;
        }
        red[tid] = ls;
        __syncthreads();
        for (int st = NTHREADS / 2; st > 0; st >>= 1) {
            if (tid < st) red[tid] += red[tid + st];
            __syncthreads();
        }
        float l = red[0];
        __syncthreads();

        const int dq = tid & 63;
        const int ch = tid >> 6;
        float acc = 0.0f;
        for (int c = ch * (SK / 4); c < (ch + 1) * (SK / 4); c++)
            acc += sc[c] * kv[(((size_t)(b * SK + c) * 2 + 1) * HKV + hkv) * DH + dq];
        red[tid] = acc;
        __syncthreads();
        if (tid < DH) {
            float o = red[tid] + red[tid + 64] + red[tid + 128] + red[tid + 192];
            out[((size_t)(b * SQ + r) * HQ + h) * DH + tid] = o / l;
        }
        __syncthreads();
    }
}

// ---------------------------------------------------------------------------
// Kernel 2: flash attention, fp32, 64x64 tiles, 8x4 per-thread register tile,
// 128 threads. S columns mapped j*16+tx -> conflict-free K fragment loads.
// ---------------------------------------------------------------------------
__global__ void __launch_bounds__(FA_THREADS, 3)
fa_kernel(const float* __restrict__ q, const float* __restrict__ kv,
          float* __restrict__ out) {
    extern __shared__ float sm[];
    float* Qs = sm;                 // [TS][TP]
    float* Ks = Qs + TS * TP;       // [TS][TP]
    float* Vs = Ks + TS * TP;       // [TS][TP]
    float* Ps = Vs + TS * TP;       // [TS][TP]
    __shared__ float biasS[TS];

    const int qt  = (SQ / TS - 1) - blockIdx.x;   // heavy tiles first
    const int bh  = blockIdx.y;
    const int b   = bh / HQ;
    const int h   = bh % HQ;
    const int hkv = h / GRP;
    const int m0  = qt * TS;

    const int tid = threadIdx.x;
    const int tx  = tid & 15;       // 16 column groups
    const int tyy = tid >> 4;       // 8 row groups of 8 rows
    const int r0  = tyy * 8;

    // ---- load Q tile ----
    const float* qg = q + ((size_t)(b * SQ + m0) * HQ + h) * DH;
    for (int i = tid; i < TS * (DH / 4); i += FA_THREADS) {
        int r = i >> 4, f = i & 15;
        float4 v = *(const float4*)(qg + (size_t)r * HQ * DH + f * 4);
        *(float4*)&Qs[r * TP + f * 4] = v;
    }

    float m_i[8], l_i[8], O[8][4];
#pragma unroll
    for (int i = 0; i < 8; i++) {
        m_i[i] = -1e30f; l_i[i] = 0.0f;
#pragma unroll
        for (int j = 0; j < 4; j++) O[i][j] = 0.0f;
    }

    const int ntiles = qt + 1;

    for (int jt = 0; jt < ntiles; ++jt) {
        const int n0 = jt * TS;
        __syncthreads();

        // ---- load K and V tiles ----
        for (int i = tid; i < TS * (DH / 4); i += FA_THREADS) {
            int r = i >> 4, f = i & 15;
            size_t off = (((size_t)(b * SK + n0 + r) * 2) * HKV + hkv) * DH + f * 4;
            float4 kvk = *(const float4*)(kv + off);
            *(float4*)&Ks[r * TP + f * 4] = kvk;
            float4 kvv = *(const float4*)(kv + off + (size_t)HKV * DH);
            *(float4*)&Vs[r * TP + f * 4] = kvv;
        }
        if (tid < TS) biasS[tid] = g_maskBias[b * SK + n0 + tid];
        __syncthreads();

        // ---- S = Q K^T : thread covers rows r0..r0+7, cols j*16+tx ----
        float S[8][4];
#pragma unroll
        for (int i = 0; i < 8; i++)
#pragma unroll
            for (int j = 0; j < 4; j++) S[i][j] = 0.0f;

#pragma unroll 2
        for (int dc = 0; dc < DH / 4; dc++) {
            float4 kf[4];
#pragma unroll
            for (int j = 0; j < 4; j++)
                kf[j] = *(const float4*)&Ks[(j * 16 + tx) * TP + dc * 4];
#pragma unroll
            for (int half = 0; half < 2; half++) {
                float4 qf[4];
#pragma unroll
                for (int ii = 0; ii < 4; ii++)
                    qf[ii] = *(const float4*)&Qs[(r0 + half * 4 + ii) * TP + dc * 4];
#pragma unroll
                for (int ii = 0; ii < 4; ii++)
#pragma unroll
                    for (int j = 0; j < 4; j++) {
                        int i = half * 4 + ii;
                        S[i][j] += qf[ii].x * kf[j].x;
                        S[i][j] += qf[ii].y * kf[j].y;
                        S[i][j] += qf[ii].z * kf[j].z;
                        S[i][j] += qf[ii].w * kf[j].w;
                    }
            }
        }

        // ---- scale + padding bias + causal replace ----
        const bool diag = (jt == qt);
        float bj[4];
#pragma unroll
        for (int j = 0; j < 4; j++) bj[j] = biasS[j * 16 + tx];
#pragma unroll
        for (int i = 0; i < 8; i++) {
            int r = m0 + r0 + i;
#pragma unroll
            for (int j = 0; j < 4; j++) {
                int c = n0 + j * 16 + tx;
                float s = S[i][j] * SCALE + bj[j];
                if (diag && c > r) s = NEGV;
                S[i][j] = s;
            }
        }

        // ---- online softmax ----
#pragma unroll
        for (int i = 0; i < 8; i++) {
            float rm = fmaxf(fmaxf(S[i][0], S[i][1]), fmaxf(S[i][2], S[i][3]));
#pragma unroll
            for (int w = 1; w < 16; w <<= 1)
                rm = fmaxf(rm, __shfl_xor_sync(0xffffffffu, rm, w));
            float m_new = fmaxf(m_i[i], rm);
            float alpha = __expf(m_i[i] - m_new);
            float s0 = __expf(S[i][0] - m_new);
            float s1 = __expf(S[i][1] - m_new);
            float s2 = __expf(S[i][2] - m_new);
            float s3 = __expf(S[i][3] - m_new);
            S[i][0] = s0; S[i][1] = s1; S[i][2] = s2; S[i][3] = s3;
            float sum = s0 + s1 + s2 + s3;
#pragma unroll
            for (int w = 1; w < 16; w <<= 1)
                sum += __shfl_xor_sync(0xffffffffu, sum, w);
            l_i[i] = l_i[i] * alpha + sum;
            m_i[i] = m_new;
#pragma unroll
            for (int j = 0; j < 4; j++) O[i][j] *= alpha;
        }

        // ---- write P to smem (canonical [row][col] layout) ----
#pragma unroll
        for (int i = 0; i < 8; i++)
#pragma unroll
            for (int j = 0; j < 4; j++)
                Ps[(r0 + i) * TP + j * 16 + tx] = S[i][j];
        __syncthreads();

        // ---- O += P V : O cols = tx*4+j ----
#pragma unroll 2
        for (int kc = 0; kc < TS / 4; kc++) {
            float4 vf[4];
#pragma unroll
            for (int qq = 0; qq < 4; qq++)
                vf[qq] = *(const float4*)&Vs[(kc * 4 + qq) * TP + tx * 4];
#pragma unroll
            for (int half = 0; half < 2; half++) {
                float4 pf[4];
#pragma unroll
                for (int ii = 0; ii < 4; ii++)
                    pf[ii] = *(const float4*)&Ps[(r0 + half * 4 + ii) * TP + kc * 4];
#pragma unroll
                for (int ii = 0; ii < 4; ii++) {
                    int i = half * 4 + ii;
                    O[i][0] += pf[ii].x * vf[0].x + pf[ii].y * vf[1].x + pf[ii].z * vf[2].x + pf[ii].w * vf[3].x;
                    O[i][1] += pf[ii].x * vf[0].y + pf[ii].y * vf[1].y + pf[ii].z * vf[2].y + pf[ii].w * vf[3].y;
                    O[i][2] += pf[ii].x * vf[0].z + pf[ii].y * vf[1].z + pf[ii].z * vf[2].z + pf[ii].w * vf[3].z;
                    O[i][3] += pf[ii].x * vf[0].w + pf[ii].y * vf[1].w + pf[ii].z * vf[2].w + pf[ii].w * vf[3].w;
                }
            }
        }
    }

    // ---- epilogue: skip degenerate rows (fixup kernel owns those) ----
#pragma unroll
    for (int i = 0; i < 8; i++) {
        if (m_i[i] > -5000.0f) {
            float inv = 1.0f / l_i[i];
            float4 ov = make_float4(O[i][0] * inv, O[i][1] * inv,
                                    O[i][2] * inv, O[i][3] * inv);
            size_t off = ((size_t)(b * SQ + m0 + r0 + i) * HQ + h) * DH + tx * 4;
            *(float4*)(out + off) = ov;
        }
    }
}

// ---------------------------------------------------------------------------
extern "C" void kernel_launch(void* const* d_in, const int* in_sizes, int n_in,
                              void* d_out, int out_size) {
    const float* q    = (const float*)d_in[0];
    const float* kv   = (const float*)d_in[1];
    const void*  mask = d_in[2];
    float* out = (float*)d_out;

    const int smem_bytes = 4 * TS * TP * sizeof(float);   // 69632
    static bool attr_set = false;
    if (!attr_set) {
        cudaFuncSetAttribute(fa_kernel,
                             cudaFuncAttributeMaxDynamicSharedMemorySize,
                             smem_bytes);
        attr_set = true;
    }

    mask_expand_kernel<<<16, 256>>>(mask);
    fix_degenerate_kernel<<<BQ * SQ, NTHREADS>>>(q, kv, out);
    dim3 grid(SQ / TS, BQ * HQ);
    fa_kernel<<<grid, FA_THREADS, smem_bytes>>>(q, kv, out);
}

// round 4
// speedup vs baseline: 11.0552x; 9.2526x over previous
#include <cuda_runtime.h>
#include <cuda_fp16.h>
#include <math.h>

// Problem constants (CrossAttention_24008867184861)
#define BQ   2
#define SQ   2048
#define SK   2048
#define HQ   16
#define HKV  4
#define GRP  (HQ / HKV)
#define DH   64
#define NEGV (-10000.0f)
#define SCALE 0.125f
#define LOG2E 1.4426950408889634f

#define TM 128            // Q rows per CTA
#define TN 64             // K cols per tile
#define THREADS 256
#define KPAD 72           // f16 row stride (144B: 16B-aligned, ldmatrix conflict-free)

__device__ float g_maskBias[BQ * SK];                         // 0 valid, NEGV padded
__device__ float g_suffv[(size_t)BQ * HKV * (SK + 1) * DH];   // suffix sums of V

// ---------------------------------------------------------------------------
// PTX helpers
// ---------------------------------------------------------------------------
static __device__ __forceinline__ unsigned smem_u32(const void* p) {
    return (unsigned)__cvta_generic_to_shared(p);
}
#define LDSM4(r0, r1, r2, r3, addr)                                            \
    asm volatile("ldmatrix.sync.aligned.m8n8.x4.shared.b16 {%0,%1,%2,%3}, [%4];" \
                 : "=r"(r0), "=r"(r1), "=r"(r2), "=r"(r3) : "r"(addr))
#define LDSM4T(r0, r1, r2, r3, addr)                                           \
    asm volatile("ldmatrix.sync.aligned.m8n8.x4.trans.shared.b16 {%0,%1,%2,%3}, [%4];" \
                 : "=r"(r0), "=r"(r1), "=r"(r2), "=r"(r3) : "r"(addr))
#define MMA16816(c, a0, a1, a2, a3, b0, b1)                                    \
    asm volatile("mma.sync.aligned.m16n8k16.row.col.f32.f16.f16.f32 "          \
                 "{%0,%1,%2,%3}, {%4,%5,%6,%7}, {%8,%9}, {%0,%1,%2,%3};"       \
                 : "+f"((c)[0]), "+f"((c)[1]), "+f"((c)[2]), "+f"((c)[3])      \
                 : "r"(a0), "r"(a1), "r"(a2), "r"(a3), "r"(b0), "r"(b1))

// exp2 on the FMA pipe: x <= 0, finite. rel err ~4e-5.
static __device__ __forceinline__ float exp2p(float x) {
    float r = rintf(x);
    float f = x - r;                       // [-0.5, 0.5]
    int   n = (int)r;
    int   e = n + 127;
    e = e < 0 ? 0 : e;                     // underflow -> exact 0
    float sc = __int_as_float(e << 23);
    float p = fmaf(f, 0.00961812911f, 0.0555041087f);
    p = fmaf(f, p, 0.240226507f);
    p = fmaf(f, p, 0.693147181f);
    p = fmaf(f, p, 1.0f);
    return sc * p;
}

// fp32 -> (hi, lo) fp16 pair packed as half2 stores
static __device__ __forceinline__ void split16(float x, __half& hi, __half& lo) {
    hi = __float2half_rn(x);
    lo = __float2half_rn(x - __half2float(hi));
}

// ---------------------------------------------------------------------------
// Prologue: mask dtype detect + expand, and V suffix sums per (b, hkv).
// ---------------------------------------------------------------------------
__global__ void __launch_bounds__(512)
prologue_kernel(const void* __restrict__ mask, const float* __restrict__ kv) {
    const int bid = blockIdx.x;
    const int b = bid >> 2, hkv = bid & 3;
    const int tid = threadIdx.x;
    const int ck = tid >> 6, d = tid & 63;
    const int CH = SK / 8;

    __shared__ float ps[8][64];
    float part = 0.0f;
    for (int c = ck * CH; c < (ck + 1) * CH; c++)
        part += kv[(((size_t)(b * SK + c) * 2 + 1) * HKV + hkv) * DH + d];
    ps[ck][d] = part;
    __syncthreads();
    float run = 0.0f;
    for (int k = ck + 1; k < 8; k++) run += ps[k][d];

    const size_t sbase = (size_t)(b * HKV + hkv) * (SK + 1);
    float acc = run;
    for (int c = (ck + 1) * CH - 1; c >= ck * CH; c--) {
        acc += kv[(((size_t)(b * SK + c) * 2 + 1) * HKV + hkv) * DH + d];
        g_suffv[(sbase + c) * DH + d] = acc;
    }
    if (ck == 0)
        g_suffv[(sbase + SK) * DH + d] = 0.0f;

    if (bid == 0) {
        const unsigned char* mb = (const unsigned char*)mask;
        bool odd = false;
        for (int i = tid; i < BQ * SK; i += 512)
            if ((i & 3) && mb[i]) odd = true;
        bool is_byte = __syncthreads_or(odd);
        const int* mi = (const int*)mask;
        for (int i = tid; i < BQ * SK; i += 512)
            g_maskBias[i] = (is_byte ? (int)mb[i] : mi[i]) ? 0.0f : NEGV;
    }
}

// ---------------------------------------------------------------------------
// Flash attention: error-compensated fp16 HMMA for QK^T (3 MMA passes:
// Qh*Kh + Ql*Kh + Qh*Kl -> near-fp32 scores), single fp16 HMMA for P*V.
// ---------------------------------------------------------------------------
__global__ void __launch_bounds__(THREADS, 2)
fa_kernel(const float* __restrict__ q, const float* __restrict__ kv,
          float* __restrict__ out) {
    extern __shared__ __align__(16) __half smp[];
    __half (*Qhs)[KPAD] = (__half (*)[KPAD])smp;                 // [TM][KPAD]
    __half (*Qls)[KPAD] = (__half (*)[KPAD])(smp + TM * KPAD);
    __half (*Khs)[KPAD] = (__half (*)[KPAD])(smp + 2 * TM * KPAD);
    __half (*Kls)[KPAD] = (__half (*)[KPAD])(smp + 2 * TM * KPAD + TN * KPAD);
    __half (*Vs)[KPAD]  = (__half (*)[KPAD])(smp + 2 * TM * KPAD + 2 * TN * KPAD);
    float* biasS = (float*)(smp + 2 * TM * KPAD + 3 * TN * KPAD);

    const int qt  = (SQ / TM - 1) - blockIdx.x;   // heavy tiles first
    const int bh  = blockIdx.y;
    const int b   = bh / HQ;
    const int h   = bh % HQ;
    const int hkv = h / GRP;
    const int m0  = qt * TM;

    const int tid  = threadIdx.x;
    const int lane = tid & 31;
    const int w    = tid >> 5;
    const int qd   = lane & 3;
    const int rl   = lane >> 2;

    // ---- load + split Q tile ----
    const float* qg = q + ((size_t)(b * SQ + m0) * HQ + h) * DH;
    for (int i = tid; i < TM * 16; i += THREADS) {
        int r = i >> 4, f = i & 15;
        float4 v = *(const float4*)(qg + (size_t)r * HQ * DH + f * 4);
        __half h0, l0, h1, l1, h2, l2, h3, l3;
        split16(v.x, h0, l0); split16(v.y, h1, l1);
        split16(v.z, h2, l2); split16(v.w, h3, l3);
        *(__half2*)&Qhs[r][f * 4]     = __halves2half2(h0, h1);
        *(__half2*)&Qhs[r][f * 4 + 2] = __halves2half2(h2, h3);
        *(__half2*)&Qls[r][f * 4]     = __halves2half2(l0, l1);
        *(__half2*)&Qls[r][f * 4 + 2] = __halves2half2(l2, l3);
    }

    float m_lo = -1e30f, m_hi = -1e30f, l_lo = 0.0f, l_hi = 0.0f;
    float O[8][4];
#pragma unroll
    for (int j = 0; j < 8; j++)
#pragma unroll
        for (int e = 0; e < 4; e++) O[j][e] = 0.0f;

    const int r_lo = m0 + w * 16 + rl;
    const int r_hi = r_lo + 8;
    const int ntiles = 2 * qt + 2;

    for (int jt = 0; jt < ntiles; jt++) {
        const int n0 = jt * TN;
        __syncthreads();
        // ---- load + split K, load V ----
        for (int i = tid; i < TN * 16; i += THREADS) {
            int r = i >> 4, f = i & 15;
            size_t off = (((size_t)(b * SK + n0 + r) * 2) * HKV + hkv) * DH + f * 4;
            float4 kk = *(const float4*)(kv + off);
            float4 vv = *(const float4*)(kv + off + (size_t)HKV * DH);
            __half h0, l0, h1, l1, h2, l2, h3, l3;
            split16(kk.x, h0, l0); split16(kk.y, h1, l1);
            split16(kk.z, h2, l2); split16(kk.w, h3, l3);
            *(__half2*)&Khs[r][f * 4]     = __halves2half2(h0, h1);
            *(__half2*)&Khs[r][f * 4 + 2] = __halves2half2(h2, h3);
            *(__half2*)&Kls[r][f * 4]     = __halves2half2(l0, l1);
            *(__half2*)&Kls[r][f * 4 + 2] = __halves2half2(l2, l3);
            *(__half2*)&Vs[r][f * 4]      = __floats2half2_rn(vv.x, vv.y);
            *(__half2*)&Vs[r][f * 4 + 2]  = __floats2half2_rn(vv.z, vv.w);
        }
        if (tid < TN) biasS[tid] = g_maskBias[b * SK + n0 + tid];
        __syncthreads();

        // ---- S = Q K^T via 3-pass compensated HMMA ----
        float S[8][4];
#pragma unroll
        for (int j = 0; j < 8; j++)
#pragma unroll
            for (int e = 0; e < 4; e++) S[j][e] = 0.0f;

        const int g = lane >> 3;
        const int arow = w * 16 + (lane & 15);
        const int acol = (lane >> 4) * 8;
#pragma unroll
        for (int ks = 0; ks < 4; ks++) {
            unsigned ah0, ah1, ah2, ah3, al0, al1, al2, al3;
            LDSM4(ah0, ah1, ah2, ah3, smem_u32(&Qhs[arow][ks * 16 + acol]));
            LDSM4(al0, al1, al2, al3, smem_u32(&Qls[arow][ks * 16 + acol]));
#pragma unroll
            for (int jp = 0; jp < 4; jp++) {
                const int brow = jp * 16 + (g >> 1) * 8 + (lane & 7);
                const int bcol = ks * 16 + (g & 1) * 8;
                unsigned bh0, bh1, bh2, bh3, bl0, bl1, bl2, bl3;
                LDSM4(bh0, bh1, bh2, bh3, smem_u32(&Khs[brow][bcol]));
                LDSM4(bl0, bl1, bl2, bl3, smem_u32(&Kls[brow][bcol]));
                MMA16816(S[2 * jp],     ah0, ah1, ah2, ah3, bh0, bh1);
                MMA16816(S[2 * jp + 1], ah0, ah1, ah2, ah3, bh2, bh3);
                MMA16816(S[2 * jp],     al0, al1, al2, al3, bh0, bh1);
                MMA16816(S[2 * jp + 1], al0, al1, al2, al3, bh2, bh3);
                MMA16816(S[2 * jp],     ah0, ah1, ah2, ah3, bl0, bl1);
                MMA16816(S[2 * jp + 1], ah0, ah1, ah2, ah3, bl2, bl3);
            }
        }

        // ---- scale + bias + causal + online softmax (FMA-pipe exp) ----
        const bool needMask = (jt >= 2 * qt);
        float mx_lo = -1e30f, mx_hi = -1e30f;
#pragma unroll
        for (int j = 0; j < 8; j++) {
            float2 bp = *(float2*)&biasS[j * 8 + qd * 2];
            int c0 = n0 + j * 8 + qd * 2, c1 = c0 + 1;
            float s0 = fmaf(S[j][0], SCALE, bp.x);
            float s1 = fmaf(S[j][1], SCALE, bp.y);
            float s2 = fmaf(S[j][2], SCALE, bp.x);
            float s3 = fmaf(S[j][3], SCALE, bp.y);
            if (needMask) {
                if (c0 > r_lo) s0 = NEGV;
                if (c1 > r_lo) s1 = NEGV;
                if (c0 > r_hi) s2 = NEGV;
                if (c1 > r_hi) s3 = NEGV;
            }
            S[j][0] = s0; S[j][1] = s1; S[j][2] = s2; S[j][3] = s3;
            mx_lo = fmaxf(mx_lo, fmaxf(s0, s1));
            mx_hi = fmaxf(mx_hi, fmaxf(s2, s3));
        }
        mx_lo = fmaxf(mx_lo, __shfl_xor_sync(0xffffffffu, mx_lo, 1));
        mx_lo = fmaxf(mx_lo, __shfl_xor_sync(0xffffffffu, mx_lo, 2));
        mx_hi = fmaxf(mx_hi, __shfl_xor_sync(0xffffffffu, mx_hi, 1));
        mx_hi = fmaxf(mx_hi, __shfl_xor_sync(0xffffffffu, mx_hi, 2));

        float mn_lo = fmaxf(m_lo, mx_lo), mn_hi = fmaxf(m_hi, mx_hi);
        float al = exp2p((m_lo - mn_lo) * LOG2E);
        float ah = exp2p((m_hi - mn_hi) * LOG2E);
        float base_lo = -mn_lo * LOG2E, base_hi = -mn_hi * LOG2E;
        float sum_lo = 0.0f, sum_hi = 0.0f;
        unsigned pf[8][2];
#pragma unroll
        for (int j = 0; j < 8; j++) {
            float p0 = exp2p(fmaf(S[j][0], LOG2E, base_lo));
            float p1 = exp2p(fmaf(S[j][1], LOG2E, base_lo));
            float p2 = exp2p(fmaf(S[j][2], LOG2E, base_hi));
            float p3 = exp2p(fmaf(S[j][3], LOG2E, base_hi));
            sum_lo += p0 + p1;
            sum_hi += p2 + p3;
            __half2 hl = __floats2half2_rn(p0, p1);
            __half2 hh = __floats2half2_rn(p2, p3);
            pf[j][0] = *(unsigned*)&hl;
            pf[j][1] = *(unsigned*)&hh;
        }
        sum_lo += __shfl_xor_sync(0xffffffffu, sum_lo, 1);
        sum_lo += __shfl_xor_sync(0xffffffffu, sum_lo, 2);
        sum_hi += __shfl_xor_sync(0xffffffffu, sum_hi, 1);
        sum_hi += __shfl_xor_sync(0xffffffffu, sum_hi, 2);
        l_lo = l_lo * al + sum_lo;
        l_hi = l_hi * ah + sum_hi;
        m_lo = mn_lo; m_hi = mn_hi;
#pragma unroll
        for (int j = 0; j < 8; j++) {
            O[j][0] *= al; O[j][1] *= al;
            O[j][2] *= ah; O[j][3] *= ah;
        }

        // ---- O += P V via HMMA (P frags from registers) ----
#pragma unroll
        for (int ks = 0; ks < 4; ks++) {
            unsigned A0 = pf[2 * ks][0], A1 = pf[2 * ks][1];
            unsigned A2 = pf[2 * ks + 1][0], A3 = pf[2 * ks + 1][1];
#pragma unroll
            for (int dp = 0; dp < 4; dp++) {
                unsigned b0, b1, b2, b3;
                unsigned vaddr = smem_u32(&Vs[ks * 16 + (g & 1) * 8 + (lane & 7)][(dp * 2 + (g >> 1)) * 8]);
                LDSM4T(b0, b1, b2, b3, vaddr);
                MMA16816(O[2 * dp],     A0, A1, A2, A3, b0, b1);
                MMA16816(O[2 * dp + 1], A0, A1, A2, A3, b2, b3);
            }
        }
    }

    // ---- epilogue: degenerate-row tail correction (rare), normalize, store ----
    bool need = (m_lo < -5000.0f) || (m_hi < -5000.0f);
    if (__any_sync(0xffffffffu, need)) {
        float mf_lo = fmaxf(m_lo, NEGV), mf_hi = fmaxf(m_hi, NEGV);
        float al = __expf(m_lo - mf_lo), ah = __expf(m_hi - mf_hi);
        float te_lo = __expf(NEGV - mf_lo), te_hi = __expf(NEGV - mf_hi);
        float ntl = (float)(SK - 1 - r_lo), nth = (float)(SK - 1 - r_hi);
        l_lo = l_lo * al + ntl * te_lo;
        l_hi = l_hi * ah + nth * te_hi;
        const size_t sbase = (size_t)(b * HKV + hkv) * (SK + 1);
        const float* sl = &g_suffv[(sbase + (r_lo + 1)) * DH];
        const float* sh = &g_suffv[(sbase + (r_hi + 1)) * DH];
#pragma unroll
        for (int j = 0; j < 8; j++) {
            int d0 = j * 8 + qd * 2;
            O[j][0] = O[j][0] * al + te_lo * sl[d0];
            O[j][1] = O[j][1] * al + te_lo * sl[d0 + 1];
            O[j][2] = O[j][2] * ah + te_hi * sh[d0];
            O[j][3] = O[j][3] * ah + te_hi * sh[d0 + 1];
        }
    }

    float il = 1.0f / l_lo, ih = 1.0f / l_hi;
    float* po  = out + ((size_t)(b * SQ + r_lo) * HQ + h) * DH;
    float* po2 = out + ((size_t)(b * SQ + r_hi) * HQ + h) * DH;
#pragma unroll
    for (int j = 0; j < 8; j++) {
        int d0 = j * 8 + qd * 2;
        *(float2*)&po[d0]  = make_float2(O[j][0] * il, O[j][1] * il);
        *(float2*)&po2[d0] = make_float2(O[j][2] * ih, O[j][3] * ih);
    }
}

// ---------------------------------------------------------------------------
extern "C" void kernel_launch(void* const* d_in, const int* in_sizes, int n_in,
                              void* d_out, int out_size) {
    const float* q    = (const float*)d_in[0];
    const float* kv   = (const float*)d_in[1];
    const void*  mask = d_in[2];
    float* out = (float*)d_out;

    const int smem_bytes = (2 * TM + 3 * TN) * KPAD * sizeof(__half)
                         + TN * sizeof(float);   // 64768 B
    static bool attr_set = false;
    if (!attr_set) {
        cudaFuncSetAttribute(fa_kernel,
                             cudaFuncAttributeMaxDynamicSharedMemorySize,
                             smem_bytes);
        attr_set = true;
    }

    prologue_kernel<<<BQ * HKV, 512>>>(mask, kv);
    dim3 grid(SQ / TM, BQ * HQ);
    fa_kernel<<<grid, THREADS, smem_bytes>>>(q, kv, out);
}